// round 2
// baseline (speedup 1.0000x reference)
#include <cuda_runtime.h>
#include <stdint.h>

// ---------------- problem constants ----------------
#define BATCH     16
#define KTOP      5000
#define NBINS     4096          // top-12-bit monotonic-float bins
#define CAND_CAP  8192
#define BK        (BATCH*KTOP)  // 80000

// supertile = 256 elements (per warp-iteration); subgroup = 32 elements
#define ST_PB   17264           // supertiles per batch: 12960+3240+810+203+51
#define NSG     (ST_PB*8)       // 138112 subgroups per batch (7 are zero-pad)

// level tables (S = 64,32,16,8,4), per-(level,batch) chunk of E = 810*S*S elems
// supertile offsets: 0, 12960, 16200, 17010, 17213, 17264
// goff (NHWC flat-score offset) = anchor_offset*90

// ---------------- scratch (no allocation allowed) ----------------
static __device__ unsigned int        d_gmax32[BATCH * ST_PB * 4];  // 2 packed sub-maxes/uint
static __device__ unsigned int        d_thresh[BATCH];
static __device__ unsigned int        d_candcnt[BATCH];
static __device__ unsigned long long  d_cand[BATCH * CAND_CAP];

__device__ __forceinline__ unsigned int ordu(float f) {
    unsigned int u = __float_as_uint(f);
    return (u & 0x80000000u) ? ~u : (u | 0x80000000u);
}

// ---------------- pass 1: stream cls, write packed subgroup maxima ----------------
__global__ __launch_bounds__(1024, 2) void k_scan(
    const float* __restrict__ c0, const float* __restrict__ c1,
    const float* __restrict__ c2, const float* __restrict__ c3,
    const float* __restrict__ c4)
{
    int b    = blockIdx.y;
    int warp = threadIdx.x >> 5;
    int lane = threadIdx.x & 31;
    for (int st = blockIdx.x * 32 + warp; st < ST_PB; st += gridDim.x * 32) {
        const float* cp; int E, stl;
        if (st < 12960)      { cp = c0; E = 3317760; stl = st;         }
        else if (st < 16200) { cp = c1; E = 829440;  stl = st - 12960; }
        else if (st < 17010) { cp = c2; E = 207360;  stl = st - 16200; }
        else if (st < 17213) { cp = c3; E = 51840;   stl = st - 17010; }
        else                 { cp = c4; E = 12960;   stl = st - 17213; }
        int m0 = stl * 256 + lane * 4;
        const float* p = cp + (size_t)b * E;
        unsigned int a = 0u, bb = 0u;
        if (m0 < E) {                       // E % 4 == 0 -> whole float4 valid
            float4 v = *(const float4*)(p + m0);
            a = max(max(ordu(v.x), ordu(v.y)), max(ordu(v.z), ordu(v.w))) >> 20;
        }
        if (m0 + 128 < E) {
            float4 v = *(const float4*)(p + m0 + 128);
            bb = max(max(ordu(v.x), ordu(v.y)), max(ordu(v.z), ordu(v.w))) >> 20;
        }
        unsigned int pk = (bb << 16) | a;   // two 12-bit maxima per word
        pk = __vmaxu2(pk, __shfl_xor_sync(0xffffffffu, pk, 1));
        pk = __vmaxu2(pk, __shfl_xor_sync(0xffffffffu, pk, 2));
        pk = __vmaxu2(pk, __shfl_xor_sync(0xffffffffu, pk, 4));
        if ((lane & 7) == 0)                // lanes 0,8,16,24 -> 4 consecutive uints
            d_gmax32[((size_t)b * ST_PB + st) * 4 + (lane >> 3)] = pk;
    }
}

// ---------------- pass 2: per-batch histogram + threshold (one block/batch) ----------------
__global__ __launch_bounds__(1024, 1) void k_thresh() {
    __shared__ unsigned int hist[NBINS];
    __shared__ unsigned int ss[1024];
    int b = blockIdx.x, t = threadIdx.x;
    for (int i = t; i < NBINS; i += 1024) hist[i] = 0u;
    __syncthreads();
    const unsigned int* gm = d_gmax32 + (size_t)b * ST_PB * 4;
    for (int i = t; i < ST_PB * 4; i += 1024) {
        unsigned int v = gm[i];
        unsigned int b0 = v & 0xffffu, b1 = v >> 16;
        unsigned int m0 = __match_any_sync(0xffffffffu, b0);
        if ((__ffs(m0) - 1) == (t & 31)) atomicAdd(&hist[b0], __popc(m0));
        unsigned int m1 = __match_any_sync(0xffffffffu, b1);
        if ((__ffs(m1) - 1) == (t & 31)) atomicAdd(&hist[b1], __popc(m1));
    }
    __syncthreads();
    unsigned int s = hist[4*t] + hist[4*t+1] + hist[4*t+2] + hist[4*t+3];
    ss[t] = s;
    for (int off = 1; off < 1024; off <<= 1) {
        __syncthreads();
        unsigned int add = (t + off < 1024) ? ss[t + off] : 0u;
        __syncthreads();
        ss[t] += add;
    }
    __syncthreads();
    unsigned int suf_excl = ss[t] - s;           // strictly-higher chunks
    if (suf_excl < (unsigned)KTOP && suf_excl + s >= (unsigned)KTOP) {
        unsigned int acc = suf_excl, tb = 0u;
        for (int bin = 4*t + 3; bin >= 4*t; --bin) {
            acc += hist[bin];
            if (acc >= (unsigned)KTOP) { tb = (unsigned)bin; break; }
        }
        d_thresh[b] = tb;
    }
    if (t == 0) d_candcnt[b] = 0u;
}

// ---------------- pass 3: compact candidates (subgroup-granular revisit) ----------------
__global__ __launch_bounds__(1024, 2) void k_compact(
    const float* __restrict__ c0, const float* __restrict__ c1,
    const float* __restrict__ c2, const float* __restrict__ c3,
    const float* __restrict__ c4)
{
    int b = blockIdx.y;
    unsigned int thr = d_thresh[b];
    int warp = threadIdx.x >> 5;
    int lane = threadIdx.x & 31;
    const unsigned short* gm =
        (const unsigned short*)d_gmax32 + (size_t)b * NSG;
    for (int base = (blockIdx.x * 32 + warp) * 32; base < NSG;
         base += gridDim.x * 32 * 32) {
        unsigned int g = gm[base + lane];            // NSG % 32 == 0
        unsigned int mask = __ballot_sync(0xffffffffu, g >= thr);
        while (mask) {
            int s = __ffs(mask) - 1; mask &= mask - 1;
            int sg = base + s;
            int st = sg >> 3, rem = sg & 7, oct = rem >> 1, half = rem & 1;
            const float* cp; int E, stl, s2sh; unsigned int goff;
            if (st < 12960)      { cp = c0; E = 3317760; stl = st;         s2sh = 12; goff = 0u;       }
            else if (st < 16200) { cp = c1; E = 829440;  stl = st - 12960; s2sh = 10; goff = 3317760u; }
            else if (st < 17010) { cp = c2; E = 207360;  stl = st - 16200; s2sh = 8;  goff = 4147200u; }
            else if (st < 17213) { cp = c3; E = 51840;   stl = st - 17010; s2sh = 6;  goff = 4354560u; }
            else                 { cp = c4; E = 12960;   stl = st - 17213; s2sh = 4;  goff = 4406400u; }
            int m = stl * 256 + half * 128 + oct * 32 + lane;
            bool ok = (m < E);
            unsigned int o = ok ? ordu(cp[(size_t)b * E + m]) : 0u;
            bool pass = ok && ((o >> 20) >= thr);
            unsigned int pm = __ballot_sync(0xffffffffu, pass);
            if (pm) {
                int leader = __ffs(pm) - 1;
                unsigned int pos = 0u;
                if (lane == leader) pos = atomicAdd(&d_candcnt[b], (unsigned)__popc(pm));
                pos = __shfl_sync(0xffffffffu, pos, leader);
                if (pass) {
                    unsigned int off = pos + __popc(pm & ((1u << lane) - 1u));
                    if (off < CAND_CAP) {
                        int ch = m >> s2sh;
                        int hw = m & ((1 << s2sh) - 1);
                        unsigned int gidx = goff + (unsigned)hw * 810u + (unsigned)ch;
                        d_cand[b * CAND_CAP + off] =
                            ((unsigned long long)o << 32) | (unsigned int)(~gidx);
                    }
                }
            }
        }
    }
}

// ---------------- pass 4: per-batch bitonic sort + decode + gather + emit ----------------
extern __shared__ unsigned long long s_keys[];
__global__ void k_sort(
    const float* __restrict__ b0, const float* __restrict__ b1,
    const float* __restrict__ b2, const float* __restrict__ b3,
    const float* __restrict__ b4, float* __restrict__ out)
{
    int b = blockIdx.x, t = threadIdx.x;
    unsigned int n = d_candcnt[b];
    if (n > CAND_CAP) n = CAND_CAP;
    for (int i = t; i < CAND_CAP; i += 1024)
        s_keys[i] = (i < (int)n) ? d_cand[b * CAND_CAP + i] : 0ull;
    __syncthreads();

    for (unsigned int k = 2; k <= CAND_CAP; k <<= 1) {
        for (unsigned int j = k >> 1; j > 0; j >>= 1) {
            for (unsigned int i = t; i < CAND_CAP; i += 1024) {
                unsigned int ix = i ^ j;
                if (ix > i) {
                    unsigned long long a = s_keys[i], c = s_keys[ix];
                    bool desc = ((i & k) == 0);
                    if ((a < c) == desc) { s_keys[i] = c; s_keys[ix] = a; }
                }
            }
            __syncthreads();
        }
    }

    for (int kk = t; kk < KTOP; kk += 1024) {
        unsigned long long key = s_keys[kk];
        unsigned int o = (unsigned int)(key >> 32);
        unsigned int g = ~((unsigned int)key);
        unsigned int bits = (o & 0x80000000u) ? (o & 0x7fffffffu) : ~o;
        float val = __uint_as_float(bits);
        unsigned int anchor = g / 90u;
        unsigned int cls = g - anchor * 90u;
        const float* bp; unsigned int aoff, S2;
        if (anchor < 36864u)      { bp = b0; aoff = 0u;     S2 = 4096u; }
        else if (anchor < 46080u) { bp = b1; aoff = 36864u; S2 = 1024u; }
        else if (anchor < 48384u) { bp = b2; aoff = 46080u; S2 = 256u;  }
        else if (anchor < 48960u) { bp = b3; aoff = 48384u; S2 = 64u;   }
        else                      { bp = b4; aoff = 48960u; S2 = 16u;   }
        unsigned int la = anchor - aoff;
        unsigned int hw = la / 9u;
        unsigned int a9 = la - hw * 9u;
        size_t base = (size_t)b * 36 * S2 + (size_t)a9 * 4 * S2 + hw;
        int ok = b * KTOP + kk;
        out[ok] = val;                                   // cls_topk  [B,K,1]
        out[BK + 4*ok + 0] = bp[base];                   // box_topk  [B,K,4]
        out[BK + 4*ok + 1] = bp[base +     S2];
        out[BK + 4*ok + 2] = bp[base + 2 * S2];
        out[BK + 4*ok + 3] = bp[base + 3 * S2];
        out[BK * 5 + ok] = (float)anchor;                // indices   [B,K]
        out[BK * 6 + ok] = (float)cls;                   // classes   [B,K]
    }
}

// ---------------- launcher ----------------
extern "C" void kernel_launch(void* const* d_in, const int* in_sizes, int n_in,
                              void* d_out, int out_size)
{
    (void)out_size;
    static const int csz[5] = {53084160, 13271040, 3317760, 829440, 207360};
    static const int bsz[5] = {2359296,  589824,   147456,  36864,  9216};
    const float* cls[5] = {0,0,0,0,0};
    const float* box[5] = {0,0,0,0,0};
    for (int i = 0; i < n_in; i++) {
        for (int l = 0; l < 5; l++) {
            if (in_sizes[i] == csz[l]) cls[l] = (const float*)d_in[i];
            if (in_sizes[i] == bsz[l]) box[l] = (const float*)d_in[i];
        }
    }

    cudaFuncSetAttribute(k_sort, cudaFuncAttributeMaxDynamicSharedMemorySize,
                         CAND_CAP * sizeof(unsigned long long));

    dim3 gs(18, BATCH);
    k_scan<<<gs, 1024>>>(cls[0], cls[1], cls[2], cls[3], cls[4]);
    k_thresh<<<BATCH, 1024>>>();
    k_compact<<<gs, 1024>>>(cls[0], cls[1], cls[2], cls[3], cls[4]);
    k_sort<<<BATCH, 1024, CAND_CAP * sizeof(unsigned long long)>>>(
        box[0], box[1], box[2], box[3], box[4], (float*)d_out);
}

// round 4
// speedup vs baseline: 1.6349x; 1.6349x over previous
#include <cuda_runtime.h>
#include <stdint.h>

// ---------------- problem constants ----------------
#define BATCH     16
#define KTOP      5000
#define NBINS     4096          // top-12-bit monotonic-float bins
#define CAND_CAP  8192
#define BK        (BATCH*KTOP)  // 80000

// supertile = 512 elements (per warp-iteration, 4 float4 loads/lane)
// subgroup  = 32 elements (gmax granularity)
#define ST_PB   8633            // supertiles/batch: 6480+1620+405+102+26
#define NSG     (ST_PB*16)      // 138128 subgroups per batch

// ---------------- scratch (no allocation allowed) ----------------
static __device__ unsigned int        d_gmax32[BATCH * ST_PB * 8];  // 2 packed 12-bit maxima/uint
static __device__ unsigned int        d_thresh[BATCH];
static __device__ unsigned int        d_candcnt[BATCH];
static __device__ unsigned long long  d_cand[BATCH * CAND_CAP];

__device__ __forceinline__ unsigned int ordu(float f) {
    unsigned int u = __float_as_uint(f);
    return (u & 0x80000000u) ? ~u : (u | 0x80000000u);
}

// ---------------- pass 1: stream cls, write packed subgroup maxima ----------------
__global__ __launch_bounds__(1024, 2) void k_scan(
    const float* __restrict__ c0, const float* __restrict__ c1,
    const float* __restrict__ c2, const float* __restrict__ c3,
    const float* __restrict__ c4)
{
    int b    = blockIdx.y;
    int warp = threadIdx.x >> 5;
    int lane = threadIdx.x & 31;
    for (int st = blockIdx.x * 32 + warp; st < ST_PB; st += gridDim.x * 32) {
        const float* cp; int E, stl;
        if (st < 6480)      { cp = c0; E = 3317760; stl = st;        }
        else if (st < 8100) { cp = c1; E = 829440;  stl = st - 6480; }
        else if (st < 8505) { cp = c2; E = 207360;  stl = st - 8100; }
        else if (st < 8607) { cp = c3; E = 51840;   stl = st - 8505; }
        else                { cp = c4; E = 12960;   stl = st - 8607; }
        const float* p = cp + (size_t)b * E;
        int m0 = stl * 512 + lane * 4;
        unsigned int q[4];
        #pragma unroll
        for (int c = 0; c < 4; c++) {
            int off = m0 + c * 128;
            unsigned int m = 0u;
            if (off < E) {                  // E%4==0 -> whole float4 valid
                float4 v = *(const float4*)(p + off);
                m = max(max(ordu(v.x), ordu(v.y)), max(ordu(v.z), ordu(v.w))) >> 20;
            }
            q[c] = m;
        }
        unsigned int pk0 = (q[1] << 16) | q[0];
        unsigned int pk1 = (q[3] << 16) | q[2];
        #pragma unroll
        for (int o = 1; o <= 4; o <<= 1) {
            pk0 = __vmaxu2(pk0, __shfl_xor_sync(0xffffffffu, pk0, o));
            pk1 = __vmaxu2(pk1, __shfl_xor_sync(0xffffffffu, pk1, o));
        }
        if ((lane & 7) == 0) {              // octet leaders: lanes 0,8,16,24
            size_t idx = ((size_t)b * ST_PB + st) * 8 + (lane >> 3) * 2;
            d_gmax32[idx]     = pk0;
            d_gmax32[idx + 1] = pk1;
        }
    }
}

// ---------------- pass 2: per-batch histogram + threshold (plain shared atomics) ----------------
__global__ __launch_bounds__(1024, 1) void k_thresh() {
    __shared__ unsigned int hist[NBINS];
    __shared__ unsigned int ss[1024];
    int b = blockIdx.x, t = threadIdx.x;
    for (int i = t; i < NBINS; i += 1024) hist[i] = 0u;
    __syncthreads();
    const unsigned int* gm = d_gmax32 + (size_t)b * ST_PB * 8;
    for (int i = t; i < ST_PB * 8; i += 1024) {   // no warp collectives: tail-safe
        unsigned int v = gm[i];
        atomicAdd(&hist[v & 0xffffu], 1u);
        atomicAdd(&hist[v >> 16], 1u);
    }
    __syncthreads();
    unsigned int s = hist[4*t] + hist[4*t+1] + hist[4*t+2] + hist[4*t+3];
    ss[t] = s;
    for (int off = 1; off < 1024; off <<= 1) {
        __syncthreads();
        unsigned int add = (t + off < 1024) ? ss[t + off] : 0u;
        __syncthreads();
        ss[t] += add;
    }
    __syncthreads();
    unsigned int suf_excl = ss[t] - s;           // strictly-higher chunks
    if (suf_excl < (unsigned)KTOP && suf_excl + s >= (unsigned)KTOP) {
        unsigned int acc = suf_excl, tb = 0u;
        for (int bin = 4*t + 3; bin >= 4*t; --bin) {
            acc += hist[bin];
            if (acc >= (unsigned)KTOP) { tb = (unsigned)bin; break; }
        }
        d_thresh[b] = tb;
    }
    if (t == 0) d_candcnt[b] = 0u;
}

// ---------------- pass 3: compact candidates (32-elem subgroup revisit) ----------------
__global__ __launch_bounds__(1024, 2) void k_compact(
    const float* __restrict__ c0, const float* __restrict__ c1,
    const float* __restrict__ c2, const float* __restrict__ c3,
    const float* __restrict__ c4)
{
    int b = blockIdx.y;
    unsigned int thr = d_thresh[b];
    int warp = threadIdx.x >> 5;
    int lane = threadIdx.x & 31;
    const unsigned short* gm = (const unsigned short*)d_gmax32 + (size_t)b * NSG;
    for (int base = (blockIdx.x * 32 + warp) * 32; base < NSG;
         base += gridDim.x * 32 * 32) {
        int i = base + lane;
        unsigned int g = (i < NSG) ? gm[i] : 0u;
        unsigned int mask = __ballot_sync(0xffffffffu, g >= thr);
        while (mask) {
            int s = __ffs(mask) - 1; mask &= mask - 1;
            int sg = base + s;
            int st = sg >> 4, o = (sg >> 2) & 3, c = sg & 3;
            const float* cp; int E, stl, s2sh; unsigned int goff;
            if (st < 6480)      { cp = c0; E = 3317760; stl = st;        s2sh = 12; goff = 0u;       }
            else if (st < 8100) { cp = c1; E = 829440;  stl = st - 6480; s2sh = 10; goff = 3317760u; }
            else if (st < 8505) { cp = c2; E = 207360;  stl = st - 8100; s2sh = 8;  goff = 4147200u; }
            else if (st < 8607) { cp = c3; E = 51840;   stl = st - 8505; s2sh = 6;  goff = 4354560u; }
            else                { cp = c4; E = 12960;   stl = st - 8607; s2sh = 4;  goff = 4406400u; }
            int m = stl * 512 + c * 128 + o * 32 + lane;   // subgroup fully valid (E%32==0)
            unsigned int ou = ordu(cp[(size_t)b * E + m]);
            bool pass = ((ou >> 20) >= thr);
            unsigned int pm = __ballot_sync(0xffffffffu, pass);
            if (pm) {
                int leader = __ffs(pm) - 1;
                unsigned int pos = 0u;
                if (lane == leader) pos = atomicAdd(&d_candcnt[b], (unsigned)__popc(pm));
                pos = __shfl_sync(0xffffffffu, pos, leader);
                if (pass) {
                    unsigned int off = pos + __popc(pm & ((1u << lane) - 1u));
                    if (off < CAND_CAP) {
                        int ch = m >> s2sh;
                        int hw = m & ((1 << s2sh) - 1);
                        unsigned int gidx = goff + (unsigned)hw * 810u + (unsigned)ch;
                        d_cand[b * CAND_CAP + off] =
                            ((unsigned long long)ou << 32) | (unsigned int)(~gidx);
                    }
                }
            }
        }
    }
}

// ---------------- pass 4a: local bitonic sort of 1024-key runs (k=2..1024) ----------------
__global__ __launch_bounds__(512, 2) void k_sort1() {
    __shared__ unsigned long long sk[1024];
    int seg = blockIdx.x, b = blockIdx.y, t = threadIdx.x;
    unsigned int n = d_candcnt[b];
    if (n > CAND_CAP) n = CAND_CAP;
    unsigned long long* cand = d_cand + (size_t)b * CAND_CAP + seg * 1024;
    int gbase = seg * 1024;
    for (int i = t; i < 1024; i += 512)
        sk[i] = (gbase + i < (int)n) ? cand[i] : 0ull;
    __syncthreads();
    for (unsigned int k = 2; k <= 1024; k <<= 1) {
        for (unsigned int j = k >> 1; j > 0; j >>= 1) {
            for (unsigned int i = t; i < 1024; i += 512) {
                unsigned int ix = i ^ j;
                if (ix > i) {
                    unsigned long long a = sk[i], c = sk[ix];
                    bool desc = (((gbase + i) & k) == 0);
                    if ((a < c) == desc) { sk[i] = c; sk[ix] = a; }
                }
            }
            __syncthreads();
        }
    }
    for (int i = t; i < 1024; i += 512) cand[i] = sk[i];
}

// ---------------- pass 4b: one global bitonic step (j >= 1024) ----------------
__global__ __launch_bounds__(1024, 2) void k_gstep(unsigned int k, unsigned int j) {
    int tid = blockIdx.x * 1024 + threadIdx.x;       // BATCH*4096 threads
    int b = tid >> 12;
    unsigned int half = (unsigned)tid & 4095u;
    unsigned int i  = ((half & ~(j - 1u)) << 1) | (half & (j - 1u));
    unsigned int ix = i + j;
    unsigned long long* c = d_cand + (size_t)b * CAND_CAP;
    unsigned long long a = c[i], d = c[ix];
    bool desc = ((i & k) == 0u);
    if ((a < d) == desc) { c[i] = d; c[ix] = a; }
}

// ---------------- pass 4c: local tail steps (j = 512..1) of merge stage k ----------------
__global__ __launch_bounds__(512, 2) void k_lstep(unsigned int k) {
    __shared__ unsigned long long sk[1024];
    int seg = blockIdx.x, b = blockIdx.y, t = threadIdx.x;
    unsigned long long* cand = d_cand + (size_t)b * CAND_CAP + seg * 1024;
    int gbase = seg * 1024;
    for (int i = t; i < 1024; i += 512) sk[i] = cand[i];
    __syncthreads();
    for (unsigned int j = 512; j > 0; j >>= 1) {
        for (unsigned int i = t; i < 1024; i += 512) {
            unsigned int ix = i ^ j;
            if (ix > i) {
                unsigned long long a = sk[i], c = sk[ix];
                bool desc = ((((unsigned)gbase + i) & k) == 0u);
                if ((a < c) == desc) { sk[i] = c; sk[ix] = a; }
            }
        }
        __syncthreads();
    }
    for (int i = t; i < 1024; i += 512) cand[i] = sk[i];
}

// ---------------- pass 5: decode + box gather + emit ----------------
__global__ __launch_bounds__(256) void k_emit(
    const float* __restrict__ b0, const float* __restrict__ b1,
    const float* __restrict__ b2, const float* __restrict__ b3,
    const float* __restrict__ b4, float* __restrict__ out)
{
    int b = blockIdx.y;
    int kk = blockIdx.x * 256 + threadIdx.x;
    if (kk >= KTOP) return;
    unsigned long long key = d_cand[(size_t)b * CAND_CAP + kk];
    unsigned int o = (unsigned int)(key >> 32);
    unsigned int g = ~((unsigned int)key);
    unsigned int bits = (o & 0x80000000u) ? (o & 0x7fffffffu) : ~o;
    float val = __uint_as_float(bits);
    unsigned int anchor = g / 90u;
    unsigned int cls = g - anchor * 90u;
    const float* bp; unsigned int aoff, S2;
    if (anchor < 36864u)      { bp = b0; aoff = 0u;     S2 = 4096u; }
    else if (anchor < 46080u) { bp = b1; aoff = 36864u; S2 = 1024u; }
    else if (anchor < 48384u) { bp = b2; aoff = 46080u; S2 = 256u;  }
    else if (anchor < 48960u) { bp = b3; aoff = 48384u; S2 = 64u;   }
    else                      { bp = b4; aoff = 48960u; S2 = 16u;   }
    unsigned int la = anchor - aoff;
    unsigned int hw = la / 9u;
    unsigned int a9 = la - hw * 9u;
    size_t base = (size_t)b * 36 * S2 + (size_t)a9 * 4 * S2 + hw;
    int ok = b * KTOP + kk;
    out[ok] = val;                                   // cls_topk  [B,K,1]
    out[BK + 4*ok + 0] = bp[base];                   // box_topk  [B,K,4]
    out[BK + 4*ok + 1] = bp[base +     S2];
    out[BK + 4*ok + 2] = bp[base + 2 * S2];
    out[BK + 4*ok + 3] = bp[base + 3 * S2];
    out[BK * 5 + ok] = (float)anchor;                // indices   [B,K]
    out[BK * 6 + ok] = (float)cls;                   // classes   [B,K]
}

// ---------------- launcher ----------------
extern "C" void kernel_launch(void* const* d_in, const int* in_sizes, int n_in,
                              void* d_out, int out_size)
{
    (void)out_size;
    static const int csz[5] = {53084160, 13271040, 3317760, 829440, 207360};
    static const int bsz[5] = {2359296,  589824,   147456,  36864,  9216};
    const float* cls[5] = {0,0,0,0,0};
    const float* box[5] = {0,0,0,0,0};
    for (int i = 0; i < n_in; i++) {
        for (int l = 0; l < 5; l++) {
            if (in_sizes[i] == csz[l]) cls[l] = (const float*)d_in[i];
            if (in_sizes[i] == bsz[l]) box[l] = (const float*)d_in[i];
        }
    }

    dim3 gs(18, BATCH);
    k_scan<<<gs, 1024>>>(cls[0], cls[1], cls[2], cls[3], cls[4]);
    k_thresh<<<BATCH, 1024>>>();
    k_compact<<<gs, 1024>>>(cls[0], cls[1], cls[2], cls[3], cls[4]);

    dim3 seg(CAND_CAP / 1024, BATCH);        // (8, 16)
    k_sort1<<<seg, 512>>>();
    int gblk = BATCH * (CAND_CAP / 2) / 1024; // 64
    // merge stage k=2048
    k_gstep<<<gblk, 1024>>>(2048u, 1024u);
    k_lstep<<<seg, 512>>>(2048u);
    // merge stage k=4096
    k_gstep<<<gblk, 1024>>>(4096u, 2048u);
    k_gstep<<<gblk, 1024>>>(4096u, 1024u);
    k_lstep<<<seg, 512>>>(4096u);
    // merge stage k=8192
    k_gstep<<<gblk, 1024>>>(8192u, 4096u);
    k_gstep<<<gblk, 1024>>>(8192u, 2048u);
    k_gstep<<<gblk, 1024>>>(8192u, 1024u);
    k_lstep<<<seg, 512>>>(8192u);

    k_emit<<<dim3((KTOP + 255) / 256, BATCH), 256>>>(
        box[0], box[1], box[2], box[3], box[4], (float*)d_out);
}

// round 5
// speedup vs baseline: 1.7498x; 1.0703x over previous
#include <cuda_runtime.h>
#include <stdint.h>

// ---------------- problem constants ----------------
#define BATCH     16
#define KTOP      5000
#define NBINS     4096          // top-12-bit monotonic-float bins
#define CAND_CAP  8192
#define BK        (BATCH*KTOP)  // 80000

// supertile = 512 elements (per warp-iteration, 4 float4 loads/lane)
// subgroup  = 32 elements (gmax granularity)
#define ST_PB   8633            // supertiles/batch: 6480+1620+405+102+26
#define NSG     (ST_PB*16)      // 138128 subgroups per batch

// ---------------- scratch (no allocation; reset by k_emit each run) ----------------
static __device__ unsigned int        d_ghist[BATCH * NBINS];       // zero-init
static __device__ unsigned int        d_candcnt[BATCH];             // zero-init
static __device__ unsigned int        d_gmax32[BATCH * ST_PB * 8];  // fully rewritten by scan
static __device__ unsigned long long  d_cand[BATCH * CAND_CAP];     // fully rewritten by sort1

__device__ __forceinline__ unsigned int ordu(float f) {
    unsigned int u = __float_as_uint(f);
    return (u & 0x80000000u) ? ~u : (u | 0x80000000u);
}

__device__ __forceinline__ void cmpswap(unsigned long long& a, unsigned long long& b,
                                        bool desc) {
    if ((a < b) == desc) { unsigned long long t = a; a = b; b = t; }
}

// ---------------- pass 1: stream cls, subgroup maxima + fused histogram ----------------
__global__ __launch_bounds__(1024, 2) void k_scan(
    const float* __restrict__ c0, const float* __restrict__ c1,
    const float* __restrict__ c2, const float* __restrict__ c3,
    const float* __restrict__ c4)
{
    __shared__ unsigned int sh[NBINS];
    int b    = blockIdx.y;
    int warp = threadIdx.x >> 5;
    int lane = threadIdx.x & 31;
    for (int i = threadIdx.x; i < NBINS; i += 1024) sh[i] = 0u;
    __syncthreads();

    for (int st = blockIdx.x * 32 + warp; st < ST_PB; st += gridDim.x * 32) {
        const float* cp; int E, stl;
        if (st < 6480)      { cp = c0; E = 3317760; stl = st;        }
        else if (st < 8100) { cp = c1; E = 829440;  stl = st - 6480; }
        else if (st < 8505) { cp = c2; E = 207360;  stl = st - 8100; }
        else if (st < 8607) { cp = c3; E = 51840;   stl = st - 8505; }
        else                { cp = c4; E = 12960;   stl = st - 8607; }
        const float* p = cp + (size_t)b * E;
        int m0 = stl * 512 + lane * 4;
        unsigned int q[4];
        #pragma unroll
        for (int c = 0; c < 4; c++) {
            int off = m0 + c * 128;
            unsigned int m = 0u;
            if (off < E) {                  // E%4==0 -> whole float4 valid
                float4 v = *(const float4*)(p + off);
                m = max(max(ordu(v.x), ordu(v.y)), max(ordu(v.z), ordu(v.w))) >> 20;
            }
            q[c] = m;
        }
        unsigned int pk0 = (q[1] << 16) | q[0];
        unsigned int pk1 = (q[3] << 16) | q[2];
        #pragma unroll
        for (int o = 1; o <= 4; o <<= 1) {
            pk0 = __vmaxu2(pk0, __shfl_xor_sync(0xffffffffu, pk0, o));
            pk1 = __vmaxu2(pk1, __shfl_xor_sync(0xffffffffu, pk1, o));
        }
        if ((lane & 7) == 0) {              // octet leaders: lanes 0,8,16,24
            size_t idx = ((size_t)b * ST_PB + st) * 8 + (lane >> 3) * 2;
            d_gmax32[idx]     = pk0;
            d_gmax32[idx + 1] = pk1;
            atomicAdd(&sh[pk0 & 0xffffu], 1u);
            atomicAdd(&sh[pk0 >> 16], 1u);
            atomicAdd(&sh[pk1 & 0xffffu], 1u);
            atomicAdd(&sh[pk1 >> 16], 1u);
        }
    }
    __syncthreads();
    for (int i = threadIdx.x; i < NBINS; i += 1024) {
        unsigned int c = sh[i];
        if (c) atomicAdd(&d_ghist[b * NBINS + i], c);   // ~50 nonzero bins/block
    }
}

// ---------------- pass 2: inline-threshold + compact candidates ----------------
__global__ __launch_bounds__(1024, 2) void k_compact(
    const float* __restrict__ c0, const float* __restrict__ c1,
    const float* __restrict__ c2, const float* __restrict__ c3,
    const float* __restrict__ c4)
{
    __shared__ unsigned int ss[1024];
    __shared__ unsigned int s_thr;
    int b = blockIdx.y;
    int t = threadIdx.x;
    // --- compute threshold from global histogram (every block, deterministic) ---
    const unsigned int* h = d_ghist + b * NBINS;
    unsigned int h0 = h[4*t], h1 = h[4*t+1], h2 = h[4*t+2], h3 = h[4*t+3];
    unsigned int s = h0 + h1 + h2 + h3;
    ss[t] = s;
    for (int off = 1; off < 1024; off <<= 1) {
        __syncthreads();
        unsigned int add = (t + off < 1024) ? ss[t + off] : 0u;
        __syncthreads();
        ss[t] += add;
    }
    __syncthreads();
    unsigned int suf_excl = ss[t] - s;               // strictly-higher chunks
    if (suf_excl < (unsigned)KTOP && suf_excl + s >= (unsigned)KTOP) {
        unsigned int acc = suf_excl + h3;
        unsigned int tb = 4*t + 3;
        if (acc < (unsigned)KTOP) { acc += h2; tb = 4*t + 2; }
        if (acc < (unsigned)KTOP) { acc += h1; tb = 4*t + 1; }
        if (acc < (unsigned)KTOP) {            tb = 4*t;     }
        s_thr = tb;
    }
    __syncthreads();
    unsigned int thr = s_thr;

    // --- compact: revisit only hot 32-elem subgroups ---
    int warp = t >> 5, lane = t & 31;
    const unsigned short* gm = (const unsigned short*)d_gmax32 + (size_t)b * NSG;
    for (int base = (blockIdx.x * 32 + warp) * 32; base < NSG;
         base += gridDim.x * 32 * 32) {
        int i = base + lane;
        unsigned int g = (i < NSG) ? gm[i] : 0u;
        unsigned int mask = __ballot_sync(0xffffffffu, g >= thr);
        while (mask) {
            int sft = __ffs(mask) - 1; mask &= mask - 1;
            int sg = base + sft;
            int st = sg >> 4, o = (sg >> 2) & 3, c = sg & 3;
            const float* cp; int E, stl, s2sh; unsigned int goff;
            if (st < 6480)      { cp = c0; E = 3317760; stl = st;        s2sh = 12; goff = 0u;       }
            else if (st < 8100) { cp = c1; E = 829440;  stl = st - 6480; s2sh = 10; goff = 3317760u; }
            else if (st < 8505) { cp = c2; E = 207360;  stl = st - 8100; s2sh = 8;  goff = 4147200u; }
            else if (st < 8607) { cp = c3; E = 51840;   stl = st - 8505; s2sh = 6;  goff = 4354560u; }
            else                { cp = c4; E = 12960;   stl = st - 8607; s2sh = 4;  goff = 4406400u; }
            int m = stl * 512 + c * 128 + o * 32 + lane;   // subgroup fully valid (E%32==0)
            unsigned int ou = ordu(cp[(size_t)b * E + m]);
            bool pass = ((ou >> 20) >= thr);
            unsigned int pm = __ballot_sync(0xffffffffu, pass);
            if (pm) {
                int leader = __ffs(pm) - 1;
                unsigned int pos = 0u;
                if (lane == leader) pos = atomicAdd(&d_candcnt[b], (unsigned)__popc(pm));
                pos = __shfl_sync(0xffffffffu, pos, leader);
                if (pass) {
                    unsigned int off = pos + __popc(pm & ((1u << lane) - 1u));
                    if (off < CAND_CAP) {
                        int ch = m >> s2sh;
                        int hw = m & ((1 << s2sh) - 1);
                        unsigned int gidx = goff + (unsigned)hw * 810u + (unsigned)ch;
                        d_cand[b * CAND_CAP + off] =
                            ((unsigned long long)ou << 32) | (unsigned int)(~gidx);
                    }
                }
            }
        }
    }
}

// ---------------- pass 3a: local bitonic sort of 1024-key runs (k=2..1024) ----------------
__global__ __launch_bounds__(512, 2) void k_sort1() {
    __shared__ unsigned long long sk[1024];
    int seg = blockIdx.x, b = blockIdx.y, t = threadIdx.x;
    unsigned int n = d_candcnt[b];
    if (n > CAND_CAP) n = CAND_CAP;
    unsigned long long* cand = d_cand + (size_t)b * CAND_CAP + seg * 1024;
    int gbase = seg * 1024;
    for (int i = t; i < 1024; i += 512)
        sk[i] = (gbase + i < (int)n) ? cand[i] : 0ull;
    __syncthreads();
    for (unsigned int k = 2; k <= 1024; k <<= 1) {
        for (unsigned int j = k >> 1; j > 0; j >>= 1) {
            for (unsigned int i = t; i < 1024; i += 512) {
                unsigned int ix = i ^ j;
                if (ix > i) {
                    unsigned long long a = sk[i], c = sk[ix];
                    bool desc = (((gbase + i) & k) == 0);
                    if ((a < c) == desc) { sk[i] = c; sk[ix] = a; }
                }
            }
            __syncthreads();
        }
    }
    for (int i = t; i < 1024; i += 512) cand[i] = sk[i];
}

// ---------------- pass 3b: full merge stage k=2048 in 2048-key shared tiles ----------------
__global__ __launch_bounds__(1024, 2) void k_m2048() {
    __shared__ unsigned long long sk[2048];
    int seg = blockIdx.x, b = blockIdx.y, t = threadIdx.x;
    unsigned long long* cand = d_cand + (size_t)b * CAND_CAP + seg * 2048;
    int gbase = seg * 2048;
    for (int i = t; i < 2048; i += 1024) sk[i] = cand[i];
    __syncthreads();
    for (unsigned int j = 1024; j > 0; j >>= 1) {
        unsigned int i  = ((t & ~(j - 1u)) << 1) | (t & (j - 1u));
        unsigned int ix = i + j;
        unsigned long long a = sk[i], c = sk[ix];
        bool desc = ((((unsigned)gbase + i) & 2048u) == 0u);
        if ((a < c) == desc) { sk[i] = c; sk[ix] = a; }
        __syncthreads();
    }
    for (int i = t; i < 2048; i += 1024) cand[i] = sk[i];
}

// ---------------- pass 3c: k=4096 global steps j=2048,1024 in registers ----------------
__global__ __launch_bounds__(1024, 2) void k_g4096() {
    int tid = blockIdx.x * 1024 + threadIdx.x;   // BATCH*2048
    int b = tid >> 11;
    unsigned int g = (unsigned)tid & 2047u;
    unsigned int high = g >> 10, low = g & 1023u;
    unsigned int i = high * 4096u + low;
    unsigned long long* c = d_cand + (size_t)b * CAND_CAP;
    unsigned long long v0 = c[i], v1 = c[i + 1024], v2 = c[i + 2048], v3 = c[i + 3072];
    bool desc = (high == 0u);                    // (idx & 4096)==0 for whole closure
    cmpswap(v0, v2, desc); cmpswap(v1, v3, desc);   // j = 2048
    cmpswap(v0, v1, desc); cmpswap(v2, v3, desc);   // j = 1024
    c[i] = v0; c[i + 1024] = v1; c[i + 2048] = v2; c[i + 3072] = v3;
}

// ---------------- pass 3d: k=8192 global steps j=4096,2048,1024 in registers ----------------
__global__ __launch_bounds__(1024, 2) void k_g8192() {
    int tid = blockIdx.x * 1024 + threadIdx.x;   // BATCH*1024
    int b = tid >> 10;
    unsigned int i = (unsigned)tid & 1023u;
    unsigned long long* c = d_cand + (size_t)b * CAND_CAP;
    unsigned long long v[8];
    #pragma unroll
    for (int m = 0; m < 8; m++) v[m] = c[i + m * 1024];
    // final merge: descending everywhere ((idx & 8192)==0 always)
    #pragma unroll
    for (int m = 0; m < 4; m++) cmpswap(v[m], v[m + 4], true);          // j=4096
    cmpswap(v[0], v[2], true); cmpswap(v[1], v[3], true);               // j=2048
    cmpswap(v[4], v[6], true); cmpswap(v[5], v[7], true);
    #pragma unroll
    for (int m = 0; m < 8; m += 2) cmpswap(v[m], v[m + 1], true);       // j=1024
    #pragma unroll
    for (int m = 0; m < 8; m++) c[i + m * 1024] = v[m];
}

// ---------------- pass 3e: local tail steps (j=512..1) of merge stage k ----------------
__global__ __launch_bounds__(512, 2) void k_ltail(unsigned int k) {
    __shared__ unsigned long long sk[1024];
    int seg = blockIdx.x, b = blockIdx.y, t = threadIdx.x;
    unsigned long long* cand = d_cand + (size_t)b * CAND_CAP + seg * 1024;
    unsigned int gbase = seg * 1024;
    for (int i = t; i < 1024; i += 512) sk[i] = cand[i];
    __syncthreads();
    for (unsigned int j = 512; j > 0; j >>= 1) {
        unsigned int i  = (((unsigned)t & ~(j - 1u)) << 1) | ((unsigned)t & (j - 1u));
        unsigned int ix = i + j;
        unsigned long long a = sk[i], c = sk[ix];
        bool desc = (((gbase + i) & k) == 0u);
        if ((a < c) == desc) { sk[i] = c; sk[ix] = a; }
        __syncthreads();
    }
    for (int i = t; i < 1024; i += 512) cand[i] = sk[i];
}

// ---------------- pass 4: decode + box gather + emit + scratch reset ----------------
__global__ __launch_bounds__(256) void k_emit(
    const float* __restrict__ b0, const float* __restrict__ b1,
    const float* __restrict__ b2, const float* __restrict__ b3,
    const float* __restrict__ b4, float* __restrict__ out)
{
    int b = blockIdx.y;
    int kk = blockIdx.x * 256 + threadIdx.x;
    // reset scratch for the next graph replay (deterministic across replays)
    if (kk < NBINS) d_ghist[b * NBINS + kk] = 0u;
    if (kk == 0)    d_candcnt[b] = 0u;
    if (kk >= KTOP) return;
    unsigned long long key = d_cand[(size_t)b * CAND_CAP + kk];
    unsigned int o = (unsigned int)(key >> 32);
    unsigned int g = ~((unsigned int)key);
    unsigned int bits = (o & 0x80000000u) ? (o & 0x7fffffffu) : ~o;
    float val = __uint_as_float(bits);
    unsigned int anchor = g / 90u;
    unsigned int cls = g - anchor * 90u;
    const float* bp; unsigned int aoff, S2;
    if (anchor < 36864u)      { bp = b0; aoff = 0u;     S2 = 4096u; }
    else if (anchor < 46080u) { bp = b1; aoff = 36864u; S2 = 1024u; }
    else if (anchor < 48384u) { bp = b2; aoff = 46080u; S2 = 256u;  }
    else if (anchor < 48960u) { bp = b3; aoff = 48384u; S2 = 64u;   }
    else                      { bp = b4; aoff = 48960u; S2 = 16u;   }
    unsigned int la = anchor - aoff;
    unsigned int hw = la / 9u;
    unsigned int a9 = la - hw * 9u;
    size_t base = (size_t)b * 36 * S2 + (size_t)a9 * 4 * S2 + hw;
    int ok = b * KTOP + kk;
    out[ok] = val;                                   // cls_topk  [B,K,1]
    out[BK + 4*ok + 0] = bp[base];                   // box_topk  [B,K,4]
    out[BK + 4*ok + 1] = bp[base +     S2];
    out[BK + 4*ok + 2] = bp[base + 2 * S2];
    out[BK + 4*ok + 3] = bp[base + 3 * S2];
    out[BK * 5 + ok] = (float)anchor;                // indices   [B,K]
    out[BK * 6 + ok] = (float)cls;                   // classes   [B,K]
}

// ---------------- launcher (9 graph nodes) ----------------
extern "C" void kernel_launch(void* const* d_in, const int* in_sizes, int n_in,
                              void* d_out, int out_size)
{
    (void)out_size;
    static const int csz[5] = {53084160, 13271040, 3317760, 829440, 207360};
    static const int bsz[5] = {2359296,  589824,   147456,  36864,  9216};
    const float* cls[5] = {0,0,0,0,0};
    const float* box[5] = {0,0,0,0,0};
    for (int i = 0; i < n_in; i++) {
        for (int l = 0; l < 5; l++) {
            if (in_sizes[i] == csz[l]) cls[l] = (const float*)d_in[i];
            if (in_sizes[i] == bsz[l]) box[l] = (const float*)d_in[i];
        }
    }

    dim3 gs(18, BATCH);
    k_scan<<<gs, 1024>>>(cls[0], cls[1], cls[2], cls[3], cls[4]);
    k_compact<<<gs, 1024>>>(cls[0], cls[1], cls[2], cls[3], cls[4]);

    k_sort1<<<dim3(8, BATCH), 512>>>();              // k = 2..1024
    k_m2048<<<dim3(4, BATCH), 1024>>>();             // k = 2048 (all steps)
    k_g4096<<<32, 1024>>>();                         // k = 4096, j = 2048,1024
    k_ltail<<<dim3(8, BATCH), 512>>>(4096u);         // k = 4096, j = 512..1
    k_g8192<<<16, 1024>>>();                         // k = 8192, j = 4096,2048,1024
    k_ltail<<<dim3(8, BATCH), 512>>>(8192u);         // k = 8192, j = 512..1

    k_emit<<<dim3((KTOP + 255) / 256, BATCH), 256>>>(
        box[0], box[1], box[2], box[3], box[4], (float*)d_out);
}